// round 13
// baseline (speedup 1.0000x reference)
#include <cuda_runtime.h>
#include <cuda_fp16.h>
#include <stdint.h>
#include <float.h>

#define DECAY 0.99f
#define OMD   0.01f
#define EPS   1e-5f
#define NROWS 32768
#define DDIM  128
#define KCODES 1024
#define BM 128                   /* rows per CTA  */
#define BN 128                   /* codes per tile */
#define NBLK (KCODES / BN)       /* 8 */
#define THREADS 256
#define MARGIN 0.05f

/* smem byte offsets */
#define OFF_X1   0               /* 128x128 fp16 swizzled, 32KB */
#define OFF_E1   32768           /* 32KB */
#define OFF_E2   65536           /* 32KB */
#define OFF_ES2  98304           /* 128 floats */
#define OFF_BI   98816           /* 128 ints  */
#define OFF_FLAG 99328           /* 128 ints  */
#define SMEM_TOTAL 99840

typedef unsigned long long ull;

/* scratch (no device mallocs allowed) */
__device__ float         g_e2[KCODES];
__device__ int           g_idx[NROWS];
__device__ float         g_sm[KCODES];
__device__ __half        g_eh1[KCODES * DDIM];
__device__ __half        g_eh2[KCODES * DDIM];
__device__ unsigned char g_flag[NROWS];

/* ------------------------------------------------------------------ */
__device__ __forceinline__ uint32_t smem_u32(const void* p) {
    uint32_t a;
    asm("{ .reg .u64 t; cvta.to.shared.u64 t, %1; cvt.u32.u64 %0, t; }"
        : "=r"(a) : "l"(p));
    return a;
}
__device__ __forceinline__ uint32_t sw128(uint32_t off) {
    return off ^ ((off >> 3) & 0x70);
}
/* blocked SW128 atom layout for [128 rows x 128 fp16] K-major tile */
__device__ __forceinline__ uint32_t blk_off(int r, int c) {
    return ((uint32_t)((c >> 6) * 16 + (r >> 3)) << 10)
         + ((uint32_t)(r & 7) << 7) + ((uint32_t)(c & 63) << 1);
}
__device__ __forceinline__ uint32_t pack_h(__half lo, __half hi) {
    uint16_t l = *reinterpret_cast<uint16_t*>(&lo);
    uint16_t h = *reinterpret_cast<uint16_t*>(&hi);
    return ((uint32_t)h << 16) | l;
}
__device__ __forceinline__ void ldsm4(uint32_t* r, uint32_t addr) {
    asm volatile("ldmatrix.sync.aligned.m8n8.x4.shared.b16 {%0,%1,%2,%3}, [%4];"
                 : "=r"(r[0]), "=r"(r[1]), "=r"(r[2]), "=r"(r[3]) : "r"(addr));
}
__device__ __forceinline__ void mma16816(float* d, const uint32_t* a,
                                         uint32_t b0, uint32_t b1) {
    asm volatile(
        "mma.sync.aligned.m16n8k16.row.col.f32.f16.f16.f32 "
        "{%0,%1,%2,%3}, {%4,%5,%6,%7}, {%8,%9}, {%0,%1,%2,%3};"
        : "+f"(d[0]), "+f"(d[1]), "+f"(d[2]), "+f"(d[3])
        : "r"(a[0]), "r"(a[1]), "r"(a[2]), "r"(a[3]), "r"(b0), "r"(b1));
}
#define CP16(dst, src) \
    asm volatile("cp.async.cg.shared.global [%0], [%1], 16;" \
                 :: "r"(dst), "l"(src) : "memory")
#define CP_COMMIT() asm volatile("cp.async.commit_group;" ::: "memory")
#define CP_WAIT(n)  asm volatile("cp.async.wait_group %0;" :: "n"(n) : "memory")

/* ------------------------------------------------------------------ */
/* embed prep: fp16 split + ||e||^2. one warp per code.                */
/* ------------------------------------------------------------------ */
__global__ void e_split_kernel(const float* __restrict__ embed) {
    int code = (blockIdx.x * blockDim.x + threadIdx.x) >> 5;
    int lane = threadIdx.x & 31;
    if (code >= KCODES) return;
    float4 a = *((const float4*)(embed + (size_t)code * DDIM) + lane);
    float f[4] = {a.x, a.y, a.z, a.w};
    __half h1[4], h2[4];
    float s = 0.f;
    #pragma unroll
    for (int j = 0; j < 4; j++) {
        s += f[j] * f[j];
        h1[j] = __float2half_rn(f[j]);
        float r = f[j] - __half2float(h1[j]);
        h2[j] = __float2half_rn(r);
    }
    uint32_t* d1 = (uint32_t*)(g_eh1 + (size_t)code * DDIM + lane * 4);
    uint32_t* d2 = (uint32_t*)(g_eh2 + (size_t)code * DDIM + lane * 4);
    d1[0] = pack_h(h1[0], h1[1]); d1[1] = pack_h(h1[2], h1[3]);
    d2[0] = pack_h(h2[0], h2[1]); d2[1] = pack_h(h2[2], h2[3]);
    #pragma unroll
    for (int o = 16; o; o >>= 1) s += __shfl_xor_sync(0xffffffffu, s, o);
    if (lane == 0) g_e2[code] = s;
}

/* ------------------------------------------------------------------ */
/* out_cs = cluster_size*DECAY ; out_avg = embed_avg*DECAY (pre-dist)  */
/* ------------------------------------------------------------------ */
__global__ void init_kernel(const float* __restrict__ cluster_size,
                            const float* __restrict__ embed_avg,
                            float* __restrict__ out_cs,
                            float* __restrict__ out_avg) {
    int i = blockIdx.x * blockDim.x + threadIdx.x;
    float4 v = *((const float4*)embed_avg + i);
    v.x *= DECAY; v.y *= DECAY; v.z *= DECAY; v.w *= DECAY;
    *((float4*)out_avg + i) = v;
    if (i < KCODES) out_cs[i] = cluster_size[i] * DECAY;
}

/* ------------------------------------------------------------------ */
/* fp16 2-pass mma.sync distance + argmax + fused gather/scatter       */
/* ------------------------------------------------------------------ */
__global__ void __launch_bounds__(THREADS, 2)
dist_mma_kernel(const float* __restrict__ x,
                const float* __restrict__ embed,
                float* __restrict__ out_q,
                float* __restrict__ out_ind,
                float* __restrict__ out_cs,
                float* __restrict__ out_avg) {
    extern __shared__ char smem[];
    const uint32_t sb = smem_u32(smem);
    const int tid  = threadIdx.x;
    const int wid  = tid >> 5, lane = tid & 31;
    const int wr   = wid & 3, wc = wid >> 2;      /* warp grid 4x2 */
    const int gid  = lane >> 2, tig = lane & 3;
    const int lrow = lane & 15, lcol = (lane >> 4) << 3;
    const int row0 = blockIdx.x * BM;
    float* es2  = (float*)(smem + OFF_ES2);       /* [128] */
    int* sbi    = (int*)(smem + OFF_BI);          /* [128] */
    int* sflag  = (int*)(smem + OFF_FLAG);        /* [128] */

    /* x tile: convert to fp16 (hi only), store swizzled */
    #pragma unroll
    for (int it = 0; it < 8; it++) {
        int i = tid + it * THREADS;
        int row = i >> 4, c8 = i & 15;
        const float* xp = x + (size_t)(row0 + row) * DDIM + c8 * 8;
        float4 fa = *(const float4*)xp;
        float4 fb = *(const float4*)(xp + 4);
        float f[8] = {fa.x, fa.y, fa.z, fa.w, fb.x, fb.y, fb.z, fb.w};
        uint32_t u1[4];
        #pragma unroll
        for (int j = 0; j < 4; j++)
            u1[j] = pack_h(__float2half_rn(f[2*j]), __float2half_rn(f[2*j+1]));
        uint32_t off = sw128(blk_off(row, c8 * 8));
        *(uint4*)(smem + OFF_X1 + off) = make_uint4(u1[0], u1[1], u1[2], u1[3]);
    }

    float m1[4], m2[4]; int i1[4];
    #pragma unroll
    for (int r = 0; r < 4; r++) { m1[r] = -FLT_MAX; m2[r] = -FLT_MAX; i1[r] = 0; }

    for (int b = 0; b < NBLK; b++) {
        __syncthreads();   /* previous iteration's compute done: E free */
        #pragma unroll
        for (int r = 0; r < 8; r++) {
            int i = tid + r * THREADS;
            int row = i >> 4, c8 = i & 15;
            uint32_t off = sw128(blk_off(row, c8 * 8));
            size_t g = (size_t)(b * BN + row) * DDIM + c8 * 8;
            CP16(sb + OFF_E1 + off, (const char*)(g_eh1 + g));
            CP16(sb + OFF_E2 + off, (const char*)(g_eh2 + g));
        }
        if (tid < BN) es2[tid] = g_e2[b * BN + tid];
        CP_COMMIT();
        CP_WAIT(0);
        __syncthreads();

        float acc[2][8][4];
        #pragma unroll
        for (int m = 0; m < 2; m++)
            #pragma unroll
            for (int j = 0; j < 8; j++)
                #pragma unroll
                for (int c = 0; c < 4; c++) acc[m][j][c] = 0.f;

        #pragma unroll
        for (int s = 0; s < 8; s++) {
            int k0 = s * 16;
            uint32_t a1[2][4];
            #pragma unroll
            for (int m = 0; m < 2; m++) {
                uint32_t off = sw128(blk_off(wr * 32 + m * 16 + lrow, k0 + lcol));
                ldsm4(a1[m], sb + OFF_X1 + off);
            }
            #pragma unroll
            for (int t = 0; t < 4; t++) {
                uint32_t q1[4], q2[4];
                uint32_t off = sw128(blk_off(wc * 64 + t * 16 + lrow, k0 + lcol));
                ldsm4(q1, sb + OFF_E1 + off);
                ldsm4(q2, sb + OFF_E2 + off);
                #pragma unroll
                for (int m = 0; m < 2; m++)
                    #pragma unroll
                    for (int h = 0; h < 2; h++) {
                        mma16816(acc[m][t * 2 + h], a1[m], q1[h], q1[h + 2]);
                        mma16816(acc[m][t * 2 + h], a1[m], q2[h], q2[h + 2]);
                    }
            }
        }

        /* argmax: k ascending per (lane,row) => strict '>' = first max */
        #pragma unroll
        for (int m = 0; m < 2; m++)
            #pragma unroll
            for (int j = 0; j < 8; j++) {
                int col = wc * 64 + j * 8 + tig * 2;
                float2 ee = *(const float2*)(es2 + col);
                int k = b * BN + col;
                #pragma unroll
                for (int h = 0; h < 2; h++) {
                    int r4 = m * 2 + h;
                    float v0 = fmaf(2.f, acc[m][j][h * 2 + 0], -ee.x);
                    float v1 = fmaf(2.f, acc[m][j][h * 2 + 1], -ee.y);
                    if (v0 > m1[r4]) { m2[r4] = m1[r4]; m1[r4] = v0; i1[r4] = k; }
                    else if (v0 > m2[r4]) m2[r4] = v0;
                    if (v1 > m1[r4]) { m2[r4] = m1[r4]; m1[r4] = v1; i1[r4] = k + 1; }
                    else if (v1 > m2[r4]) m2[r4] = v1;
                }
            }
    }

    /* cross-warp reduction: 8 candidates per row (reuse E region) */
    __syncthreads();
    float* red_m1 = (float*)(smem + OFF_E1);            /* [128][8] */
    float* red_m2 = red_m1 + BM * 8;
    int*   red_i1 = (int*)(red_m2 + BM * 8);
    #pragma unroll
    for (int r4 = 0; r4 < 4; r4++) {
        int row = wr * 32 + (r4 >> 1) * 16 + (r4 & 1) * 8 + gid;
        int slot = wc * 4 + tig;
        red_m1[row * 8 + slot] = m1[r4];
        red_m2[row * 8 + slot] = m2[r4];
        red_i1[row * 8 + slot] = i1[r4];
    }
    __syncthreads();
    if (tid < BM) {
        float bm1 = -FLT_MAX, bm2 = -FLT_MAX; int bi = 0x7fffffff;
        #pragma unroll
        for (int s = 0; s < 8; s++) {
            float em1 = red_m1[tid * 8 + s];
            float em2 = red_m2[tid * 8 + s];
            int   ei  = red_i1[tid * 8 + s];
            if (em1 > bm1 || (em1 == bm1 && ei < bi)) {
                bm2 = fmaxf(bm1, em2); bm1 = em1; bi = ei;
            } else {
                bm2 = fmaxf(bm2, em1);
            }
        }
        int row = row0 + tid;
        int fl = (bm1 - bm2 < MARGIN) ? 1 : 0;
        g_idx[row]   = bi;
        out_ind[row] = (float)bi;
        g_flag[row]  = (unsigned char)fl;
        sbi[tid]  = bi;
        sflag[tid] = fl;
    }
    __syncthreads();

    /* fused gather + EMA scatter for unflagged rows.
       thread -> (row = tid>>1, half = tid&1): 16 float4 each. */
    {
        int row  = tid >> 1;
        int half = tid & 1;
        if (!sflag[row]) {
            int k = sbi[row];
            const float4* esrc = (const float4*)(embed + (size_t)k * DDIM) + half * 16;
            const float4* xsrc = (const float4*)(x + (size_t)(row0 + row) * DDIM) + half * 16;
            float4* qdst = (float4*)(out_q + (size_t)(row0 + row) * DDIM) + half * 16;
            float*  adst = out_avg + (size_t)k * DDIM + half * 64;
            #pragma unroll 4
            for (int j = 0; j < 16; j++) {
                float4 ev = esrc[j];
                qdst[j] = ev;
                float4 xv = xsrc[j];
                atomicAdd(adst + j * 4 + 0, OMD * xv.x);
                atomicAdd(adst + j * 4 + 1, OMD * xv.y);
                atomicAdd(adst + j * 4 + 2, OMD * xv.z);
                atomicAdd(adst + j * 4 + 3, OMD * xv.w);
            }
            if (half == 0) atomicAdd(out_cs + k, OMD);
        }
    }
}

/* ------------------------------------------------------------------ */
/* exact fp32 rescue for flagged rows: argmax + gather + scatter       */
/* ------------------------------------------------------------------ */
__global__ void fixer_kernel(const float* __restrict__ x,
                             const float* __restrict__ embed,
                             float* __restrict__ out_q,
                             float* __restrict__ out_ind,
                             float* __restrict__ out_cs,
                             float* __restrict__ out_avg) {
    int w = (blockIdx.x * blockDim.x + threadIdx.x) >> 5;
    int lane = threadIdx.x & 31;
    if (w >= NROWS || !g_flag[w]) return;
    float4 xv = *((const float4*)(x + (size_t)w * DDIM) + lane);
    float best = -FLT_MAX; int bi = 0;
    for (int k = 0; k < KCODES; k++) {
        float4 ev = *((const float4*)(embed + (size_t)k * DDIM) + lane);
        float p = xv.x * ev.x + xv.y * ev.y + xv.z * ev.z + xv.w * ev.w;
        #pragma unroll
        for (int o = 16; o; o >>= 1) p += __shfl_xor_sync(0xffffffffu, p, o);
        float s = 2.f * p - g_e2[k];
        if (s > best) { best = s; bi = k; }   /* first max wins */
    }
    if (lane == 0) { g_idx[w] = bi; out_ind[w] = (float)bi; }
    /* gather + scatter for this row */
    float4 ev = *((const float4*)(embed + (size_t)bi * DDIM) + lane);
    *((float4*)(out_q + (size_t)w * DDIM) + lane) = ev;
    float* adst = out_avg + (size_t)bi * DDIM + lane * 4;
    atomicAdd(adst + 0, OMD * xv.x);
    atomicAdd(adst + 1, OMD * xv.y);
    atomicAdd(adst + 2, OMD * xv.z);
    atomicAdd(adst + 3, OMD * xv.w);
    if (lane == 0) atomicAdd(out_cs + bi, OMD);
}

/* ------------------------------------------------------------------ */
/* smoothed normalize                                                  */
/* ------------------------------------------------------------------ */
__global__ void finalize1_kernel(const float* __restrict__ out_cs) {
    __shared__ float red[KCODES];
    int tid = threadIdx.x;
    float c = out_cs[tid];
    red[tid] = c;
    __syncthreads();
    for (int s = 512; s; s >>= 1) {
        if (tid < s) red[tid] += red[tid + s];
        __syncthreads();
    }
    float total = red[0];
    g_sm[tid] = (c + EPS) / (total + KCODES * EPS) * total;
}

__global__ void finalize2_kernel(const float* __restrict__ out_avg,
                                 float* __restrict__ out_ne) {
    int i = blockIdx.x * blockDim.x + threadIdx.x;
    float sm = g_sm[i >> 5];
    float4 v = *((const float4*)out_avg + i);
    v.x /= sm; v.y /= sm; v.z /= sm; v.w /= sm;
    *((float4*)out_ne + i) = v;
}

/* ------------------------------------------------------------------ */
extern "C" void kernel_launch(void* const* d_in, const int* in_sizes, int n_in,
                              void* d_out, int out_size) {
    const float* x            = (const float*)d_in[0];
    const float* embed        = (const float*)d_in[1];
    const float* cluster_size = (const float*)d_in[2];
    const float* embed_avg    = (const float*)d_in[3];

    float* out      = (float*)d_out;
    float* out_q    = out;                               /* 32768*128 */
    float* out_ind  = out_q  + (size_t)NROWS * DDIM;     /* 32768     */
    float* out_cs   = out_ind + NROWS;                   /* 1024      */
    float* out_avg  = out_cs + KCODES;                   /* 1024*128  */
    float* out_ne   = out_avg + (size_t)KCODES * DDIM;   /* 1024*128  */

    cudaFuncSetAttribute(dist_mma_kernel,
                         cudaFuncAttributeMaxDynamicSharedMemorySize, SMEM_TOTAL);

    e_split_kernel<<<KCODES * 32 / THREADS, THREADS>>>(embed);
    init_kernel<<<KCODES * DDIM / 4 / THREADS, THREADS>>>(cluster_size, embed_avg,
                                                          out_cs, out_avg);
    dist_mma_kernel<<<NROWS / BM, THREADS, SMEM_TOTAL>>>(x, embed, out_q, out_ind,
                                                         out_cs, out_avg);
    fixer_kernel<<<NROWS * 32 / THREADS, THREADS>>>(x, embed, out_q, out_ind,
                                                    out_cs, out_avg);
    finalize1_kernel<<<1, KCODES>>>(out_cs);
    finalize2_kernel<<<KCODES * DDIM / 4 / THREADS, THREADS>>>(out_avg, out_ne);
}

// round 15
// speedup vs baseline: 1.0628x; 1.0628x over previous
#include <cuda_runtime.h>
#include <cuda_fp16.h>
#include <stdint.h>
#include <float.h>

#define DECAY 0.99f
#define OMD   0.01f
#define EPS   1e-5f
#define NROWS 32768
#define DDIM  128
#define KCODES 1024
#define BM 128                   /* rows per CTA  */
#define BN 128                   /* codes per tile */
#define NBLK (KCODES / BN)       /* 8 */
#define THREADS 256
#define MARGIN 0.05f

/* smem byte offsets */
#define OFF_X1   0               /* 128x128 fp16 swizzled, 32KB */
#define OFF_E1   32768           /* 32KB */
#define OFF_E2   65536           /* 32KB */
#define OFF_ES2  98304           /* 128 floats */
#define OFF_BI   98816           /* 128 ints  */
#define OFF_FLAG 99328           /* 128 ints  */
#define SMEM_TOTAL 99840

typedef unsigned long long ull;

/* scratch (no device mallocs allowed) */
__device__ float         g_e2[KCODES];
__device__ int           g_idx[NROWS];
__device__ float         g_sm[KCODES];
__device__ __half        g_eh1[KCODES * DDIM];
__device__ __half        g_eh2[KCODES * DDIM];
__device__ int           g_cnt;
__device__ int           g_list[NROWS];

/* ------------------------------------------------------------------ */
__device__ __forceinline__ uint32_t smem_u32(const void* p) {
    uint32_t a;
    asm("{ .reg .u64 t; cvta.to.shared.u64 t, %1; cvt.u32.u64 %0, t; }"
        : "=r"(a) : "l"(p));
    return a;
}
__device__ __forceinline__ uint32_t sw128(uint32_t off) {
    return off ^ ((off >> 3) & 0x70);
}
/* blocked SW128 atom layout for [128 rows x 128 fp16] K-major tile */
__device__ __forceinline__ uint32_t blk_off(int r, int c) {
    return ((uint32_t)((c >> 6) * 16 + (r >> 3)) << 10)
         + ((uint32_t)(r & 7) << 7) + ((uint32_t)(c & 63) << 1);
}
__device__ __forceinline__ uint32_t pack_h(__half lo, __half hi) {
    uint16_t l = *reinterpret_cast<uint16_t*>(&lo);
    uint16_t h = *reinterpret_cast<uint16_t*>(&hi);
    return ((uint32_t)h << 16) | l;
}
__device__ __forceinline__ void ldsm4(uint32_t* r, uint32_t addr) {
    asm volatile("ldmatrix.sync.aligned.m8n8.x4.shared.b16 {%0,%1,%2,%3}, [%4];"
                 : "=r"(r[0]), "=r"(r[1]), "=r"(r[2]), "=r"(r[3]) : "r"(addr));
}
__device__ __forceinline__ void mma16816(float* d, const uint32_t* a,
                                         uint32_t b0, uint32_t b1) {
    asm volatile(
        "mma.sync.aligned.m16n8k16.row.col.f32.f16.f16.f32 "
        "{%0,%1,%2,%3}, {%4,%5,%6,%7}, {%8,%9}, {%0,%1,%2,%3};"
        : "+f"(d[0]), "+f"(d[1]), "+f"(d[2]), "+f"(d[3])
        : "r"(a[0]), "r"(a[1]), "r"(a[2]), "r"(a[3]), "r"(b0), "r"(b1));
}
#define CP16(dst, src) \
    asm volatile("cp.async.cg.shared.global [%0], [%1], 16;" \
                 :: "r"(dst), "l"(src) : "memory")
#define CP_COMMIT() asm volatile("cp.async.commit_group;" ::: "memory")
#define CP_WAIT(n)  asm volatile("cp.async.wait_group %0;" :: "n"(n) : "memory")

/* ------------------------------------------------------------------ */
/* embed prep: fp16 split + ||e||^2. one warp per code.                */
/* ------------------------------------------------------------------ */
__global__ void e_split_kernel(const float* __restrict__ embed) {
    int code = (blockIdx.x * blockDim.x + threadIdx.x) >> 5;
    int lane = threadIdx.x & 31;
    if (code >= KCODES) return;
    float4 a = *((const float4*)(embed + (size_t)code * DDIM) + lane);
    float f[4] = {a.x, a.y, a.z, a.w};
    __half h1[4], h2[4];
    float s = 0.f;
    #pragma unroll
    for (int j = 0; j < 4; j++) {
        s += f[j] * f[j];
        h1[j] = __float2half_rn(f[j]);
        float r = f[j] - __half2float(h1[j]);
        h2[j] = __float2half_rn(r);
    }
    uint32_t* d1 = (uint32_t*)(g_eh1 + (size_t)code * DDIM + lane * 4);
    uint32_t* d2 = (uint32_t*)(g_eh2 + (size_t)code * DDIM + lane * 4);
    d1[0] = pack_h(h1[0], h1[1]); d1[1] = pack_h(h1[2], h1[3]);
    d2[0] = pack_h(h2[0], h2[1]); d2[1] = pack_h(h2[2], h2[3]);
    #pragma unroll
    for (int o = 16; o; o >>= 1) s += __shfl_xor_sync(0xffffffffu, s, o);
    if (lane == 0) g_e2[code] = s;
}

/* ------------------------------------------------------------------ */
/* out_cs = cluster_size*DECAY ; out_avg = embed_avg*DECAY; cnt = 0    */
/* ------------------------------------------------------------------ */
__global__ void init_kernel(const float* __restrict__ cluster_size,
                            const float* __restrict__ embed_avg,
                            float* __restrict__ out_cs,
                            float* __restrict__ out_avg) {
    int i = blockIdx.x * blockDim.x + threadIdx.x;
    if (i == 0) g_cnt = 0;
    float4 v = *((const float4*)embed_avg + i);
    v.x *= DECAY; v.y *= DECAY; v.z *= DECAY; v.w *= DECAY;
    *((float4*)out_avg + i) = v;
    if (i < KCODES) out_cs[i] = cluster_size[i] * DECAY;
}

/* ------------------------------------------------------------------ */
/* fp16 2-pass mma.sync distance + argmax + fused gather/scatter       */
/* ------------------------------------------------------------------ */
__global__ void __launch_bounds__(THREADS, 2)
dist_mma_kernel(const float* __restrict__ x,
                const float* __restrict__ embed,
                float* __restrict__ out_q,
                float* __restrict__ out_ind,
                float* __restrict__ out_cs,
                float* __restrict__ out_avg) {
    extern __shared__ char smem[];
    const uint32_t sb = smem_u32(smem);
    const int tid  = threadIdx.x;
    const int wid  = tid >> 5, lane = tid & 31;
    const int wr   = wid & 3, wc = wid >> 2;      /* warp grid 4x2 */
    const int gid  = lane >> 2, tig = lane & 3;
    const int lrow = lane & 15, lcol = (lane >> 4) << 3;
    const int row0 = blockIdx.x * BM;
    float* es2  = (float*)(smem + OFF_ES2);       /* [128] */
    int* sbi    = (int*)(smem + OFF_BI);          /* [128] */
    int* sflag  = (int*)(smem + OFF_FLAG);        /* [128] */

    /* x tile: convert to fp16 (hi only), store swizzled */
    #pragma unroll
    for (int it = 0; it < 8; it++) {
        int i = tid + it * THREADS;
        int row = i >> 4, c8 = i & 15;
        const float* xp = x + (size_t)(row0 + row) * DDIM + c8 * 8;
        float4 fa = *(const float4*)xp;
        float4 fb = *(const float4*)(xp + 4);
        float f[8] = {fa.x, fa.y, fa.z, fa.w, fb.x, fb.y, fb.z, fb.w};
        uint32_t u1[4];
        #pragma unroll
        for (int j = 0; j < 4; j++)
            u1[j] = pack_h(__float2half_rn(f[2*j]), __float2half_rn(f[2*j+1]));
        uint32_t off = sw128(blk_off(row, c8 * 8));
        *(uint4*)(smem + OFF_X1 + off) = make_uint4(u1[0], u1[1], u1[2], u1[3]);
    }

    float m1[4], m2[4]; int i1[4];
    #pragma unroll
    for (int r = 0; r < 4; r++) { m1[r] = -FLT_MAX; m2[r] = -FLT_MAX; i1[r] = 0; }

    for (int b = 0; b < NBLK; b++) {
        __syncthreads();   /* previous iteration's compute done: E free */
        #pragma unroll
        for (int r = 0; r < 8; r++) {
            int i = tid + r * THREADS;
            int row = i >> 4, c8 = i & 15;
            uint32_t off = sw128(blk_off(row, c8 * 8));
            size_t g = (size_t)(b * BN + row) * DDIM + c8 * 8;
            CP16(sb + OFF_E1 + off, (const char*)(g_eh1 + g));
            CP16(sb + OFF_E2 + off, (const char*)(g_eh2 + g));
        }
        if (tid < BN) es2[tid] = g_e2[b * BN + tid];
        CP_COMMIT();
        CP_WAIT(0);
        __syncthreads();

        float acc[2][8][4];
        #pragma unroll
        for (int m = 0; m < 2; m++)
            #pragma unroll
            for (int j = 0; j < 8; j++)
                #pragma unroll
                for (int c = 0; c < 4; c++) acc[m][j][c] = 0.f;

        #pragma unroll
        for (int s = 0; s < 8; s++) {
            int k0 = s * 16;
            uint32_t a1[2][4];
            #pragma unroll
            for (int m = 0; m < 2; m++) {
                uint32_t off = sw128(blk_off(wr * 32 + m * 16 + lrow, k0 + lcol));
                ldsm4(a1[m], sb + OFF_X1 + off);
            }
            #pragma unroll
            for (int t = 0; t < 4; t++) {
                uint32_t q1[4], q2[4];
                uint32_t off = sw128(blk_off(wc * 64 + t * 16 + lrow, k0 + lcol));
                ldsm4(q1, sb + OFF_E1 + off);
                ldsm4(q2, sb + OFF_E2 + off);
                #pragma unroll
                for (int m = 0; m < 2; m++)
                    #pragma unroll
                    for (int h = 0; h < 2; h++) {
                        mma16816(acc[m][t * 2 + h], a1[m], q1[h], q1[h + 2]);
                        mma16816(acc[m][t * 2 + h], a1[m], q2[h], q2[h + 2]);
                    }
            }
        }

        /* argmax: k ascending per (lane,row) => strict '>' = first max */
        #pragma unroll
        for (int m = 0; m < 2; m++)
            #pragma unroll
            for (int j = 0; j < 8; j++) {
                int col = wc * 64 + j * 8 + tig * 2;
                float2 ee = *(const float2*)(es2 + col);
                int k = b * BN + col;
                #pragma unroll
                for (int h = 0; h < 2; h++) {
                    int r4 = m * 2 + h;
                    float v0 = fmaf(2.f, acc[m][j][h * 2 + 0], -ee.x);
                    float v1 = fmaf(2.f, acc[m][j][h * 2 + 1], -ee.y);
                    if (v0 > m1[r4]) { m2[r4] = m1[r4]; m1[r4] = v0; i1[r4] = k; }
                    else if (v0 > m2[r4]) m2[r4] = v0;
                    if (v1 > m1[r4]) { m2[r4] = m1[r4]; m1[r4] = v1; i1[r4] = k + 1; }
                    else if (v1 > m2[r4]) m2[r4] = v1;
                }
            }
    }

    /* cross-warp reduction: 8 candidates per row (reuse E region) */
    __syncthreads();
    float* red_m1 = (float*)(smem + OFF_E1);            /* [128][8] */
    float* red_m2 = red_m1 + BM * 8;
    int*   red_i1 = (int*)(red_m2 + BM * 8);
    #pragma unroll
    for (int r4 = 0; r4 < 4; r4++) {
        int row = wr * 32 + (r4 >> 1) * 16 + (r4 & 1) * 8 + gid;
        int slot = wc * 4 + tig;
        red_m1[row * 8 + slot] = m1[r4];
        red_m2[row * 8 + slot] = m2[r4];
        red_i1[row * 8 + slot] = i1[r4];
    }
    __syncthreads();
    if (tid < BM) {
        float bm1 = -FLT_MAX, bm2 = -FLT_MAX; int bi = 0x7fffffff;
        #pragma unroll
        for (int s = 0; s < 8; s++) {
            float em1 = red_m1[tid * 8 + s];
            float em2 = red_m2[tid * 8 + s];
            int   ei  = red_i1[tid * 8 + s];
            if (em1 > bm1 || (em1 == bm1 && ei < bi)) {
                bm2 = fmaxf(bm1, em2); bm1 = em1; bi = ei;
            } else {
                bm2 = fmaxf(bm2, em1);
            }
        }
        int row = row0 + tid;
        int fl = (bm1 - bm2 < MARGIN) ? 1 : 0;
        g_idx[row]   = bi;
        out_ind[row] = (float)bi;
        if (fl) { int p = atomicAdd(&g_cnt, 1); g_list[p] = row; }
        sbi[tid]  = bi;
        sflag[tid] = fl;
    }
    __syncthreads();

    /* fused gather + EMA scatter for unflagged rows.
       thread -> (row = tid>>1, half = tid&1): 16 float4 each. */
    {
        int row  = tid >> 1;
        int half = tid & 1;
        if (!sflag[row]) {
            int k = sbi[row];
            const float4* esrc = (const float4*)(embed + (size_t)k * DDIM) + half * 16;
            const float4* xsrc = (const float4*)(x + (size_t)(row0 + row) * DDIM) + half * 16;
            float4* qdst = (float4*)(out_q + (size_t)(row0 + row) * DDIM) + half * 16;
            float*  adst = out_avg + (size_t)k * DDIM + half * 64;
            #pragma unroll 4
            for (int j = 0; j < 16; j++) {
                float4 ev = esrc[j];
                qdst[j] = ev;
                float4 xv = xsrc[j];
                atomicAdd(adst + j * 4 + 0, OMD * xv.x);
                atomicAdd(adst + j * 4 + 1, OMD * xv.y);
                atomicAdd(adst + j * 4 + 2, OMD * xv.z);
                atomicAdd(adst + j * 4 + 3, OMD * xv.w);
            }
            if (half == 0) atomicAdd(out_cs + k, OMD);
        }
    }
}

/* ------------------------------------------------------------------ */
/* exact fp32 rescue: ONE CTA per flagged row (compacted list).        */
/* 256 threads; thread t owns codes t, t+256, t+512, t+768 (4 chains   */
/* for MLP). First-max semantics: strict '>' with ascending k per      */
/* chain + lower-index tie-break across chains/threads.                */
/* ------------------------------------------------------------------ */
__global__ void __launch_bounds__(256)
fixer_kernel(const float* __restrict__ x,
             const float* __restrict__ embed,
             float* __restrict__ out_q,
             float* __restrict__ out_ind,
             float* __restrict__ out_cs,
             float* __restrict__ out_avg) {
    __shared__ float xs[DDIM];
    __shared__ float rv[256];
    __shared__ int   ri[256];
    const int tid = threadIdx.x;
    const int nflag = g_cnt;

    for (int it = blockIdx.x; it < nflag; it += gridDim.x) {
        int row = g_list[it];
        if (tid < 32)
            ((float4*)xs)[tid] = ((const float4*)(x + (size_t)row * DDIM))[tid];
        __syncthreads();

        float best = -FLT_MAX; int bk = 0x7fffffff;
        #pragma unroll
        for (int c = 0; c < 4; c++) {
            int k = tid + c * 256;
            const float4* ep = (const float4*)(embed + (size_t)k * DDIM);
            float s0 = 0.f, s1 = 0.f, s2 = 0.f, s3 = 0.f;
            #pragma unroll
            for (int j = 0; j < 32; j += 4) {
                float4 e0 = ep[j], e1 = ep[j+1], e2 = ep[j+2], e3 = ep[j+3];
                float4 x0 = ((const float4*)xs)[j];
                float4 x1 = ((const float4*)xs)[j+1];
                float4 x2 = ((const float4*)xs)[j+2];
                float4 x3 = ((const float4*)xs)[j+3];
                s0 = fmaf(x0.x,e0.x,fmaf(x0.y,e0.y,fmaf(x0.z,e0.z,fmaf(x0.w,e0.w,s0))));
                s1 = fmaf(x1.x,e1.x,fmaf(x1.y,e1.y,fmaf(x1.z,e1.z,fmaf(x1.w,e1.w,s1))));
                s2 = fmaf(x2.x,e2.x,fmaf(x2.y,e2.y,fmaf(x2.z,e2.z,fmaf(x2.w,e2.w,s2))));
                s3 = fmaf(x3.x,e3.x,fmaf(x3.y,e3.y,fmaf(x3.z,e3.z,fmaf(x3.w,e3.w,s3))));
            }
            float p = (s0 + s1) + (s2 + s3);
            float sd = 2.f * p - g_e2[k];
            if (sd > best || (sd == best && k < bk)) { best = sd; bk = k; }
        }
        rv[tid] = best; ri[tid] = bk;
        __syncthreads();
        for (int s = 128; s; s >>= 1) {
            if (tid < s) {
                float ov = rv[tid + s]; int oi = ri[tid + s];
                if (ov > rv[tid] || (ov == rv[tid] && oi < ri[tid])) {
                    rv[tid] = ov; ri[tid] = oi;
                }
            }
            __syncthreads();
        }
        int bi = ri[0];
        if (tid == 0) { g_idx[row] = bi; out_ind[row] = (float)bi; }
        if (tid < 32) {
            float4 ev = ((const float4*)(embed + (size_t)bi * DDIM))[tid];
            ((float4*)(out_q + (size_t)row * DDIM))[tid] = ev;
            float4 xv = ((const float4*)xs)[tid];
            float* adst = out_avg + (size_t)bi * DDIM + tid * 4;
            atomicAdd(adst + 0, OMD * xv.x);
            atomicAdd(adst + 1, OMD * xv.y);
            atomicAdd(adst + 2, OMD * xv.z);
            atomicAdd(adst + 3, OMD * xv.w);
            if (tid == 0) atomicAdd(out_cs + bi, OMD);
        }
        __syncthreads();   /* xs/rv/ri reused next iteration */
    }
}

/* ------------------------------------------------------------------ */
/* smoothed normalize                                                  */
/* ------------------------------------------------------------------ */
__global__ void finalize1_kernel(const float* __restrict__ out_cs) {
    __shared__ float red[KCODES];
    int tid = threadIdx.x;
    float c = out_cs[tid];
    red[tid] = c;
    __syncthreads();
    for (int s = 512; s; s >>= 1) {
        if (tid < s) red[tid] += red[tid + s];
        __syncthreads();
    }
    float total = red[0];
    g_sm[tid] = (c + EPS) / (total + KCODES * EPS) * total;
}

__global__ void finalize2_kernel(const float* __restrict__ out_avg,
                                 float* __restrict__ out_ne) {
    int i = blockIdx.x * blockDim.x + threadIdx.x;
    float sm = g_sm[i >> 5];
    float4 v = *((const float4*)out_avg + i);
    v.x /= sm; v.y /= sm; v.z /= sm; v.w /= sm;
    *((float4*)out_ne + i) = v;
}

/* ------------------------------------------------------------------ */
extern "C" void kernel_launch(void* const* d_in, const int* in_sizes, int n_in,
                              void* d_out, int out_size) {
    const float* x            = (const float*)d_in[0];
    const float* embed        = (const float*)d_in[1];
    const float* cluster_size = (const float*)d_in[2];
    const float* embed_avg    = (const float*)d_in[3];

    float* out      = (float*)d_out;
    float* out_q    = out;                               /* 32768*128 */
    float* out_ind  = out_q  + (size_t)NROWS * DDIM;     /* 32768     */
    float* out_cs   = out_ind + NROWS;                   /* 1024      */
    float* out_avg  = out_cs + KCODES;                   /* 1024*128  */
    float* out_ne   = out_avg + (size_t)KCODES * DDIM;   /* 1024*128  */

    cudaFuncSetAttribute(dist_mma_kernel,
                         cudaFuncAttributeMaxDynamicSharedMemorySize, SMEM_TOTAL);

    e_split_kernel<<<KCODES * 32 / THREADS, THREADS>>>(embed);
    init_kernel<<<KCODES * DDIM / 4 / THREADS, THREADS>>>(cluster_size, embed_avg,
                                                          out_cs, out_avg);
    dist_mma_kernel<<<NROWS / BM, THREADS, SMEM_TOTAL>>>(x, embed, out_q, out_ind,
                                                         out_cs, out_avg);
    fixer_kernel<<<1024, 256>>>(x, embed, out_q, out_ind, out_cs, out_avg);
    finalize1_kernel<<<1, KCODES>>>(out_cs);
    finalize2_kernel<<<KCODES * DDIM / 4 / THREADS, THREADS>>>(out_avg, out_ne);
}